// round 3
// baseline (speedup 1.0000x reference)
#include <cuda_runtime.h>
#include <cstdint>

#define NN 50000
#define EE 800000
#define DD 256

// ---------------- scratch (static device globals; no allocation) ----------------
__device__ int   g_deg[NN];
__device__ int   g_row_ptr[NN + 1];
__device__ int   g_cursor[NN];
__device__ int   g_col[EE];
__device__ __align__(16) float g_mean[(size_t)NN * DD];   // aggregated (mean) features
__device__ __align__(16) float g_h[(size_t)NN * DD];      // layer-1 output
__device__ __align__(16) float g_B1[512 * DD];            // [Wl^T ; Wr^T] layer 1, k-major
__device__ __align__(16) float g_B2[512 * DD];            // layer 2

// ---------------- CSR build ----------------
__global__ void zero_deg_kernel(const float* __restrict__ dummy) {
    int i = blockIdx.x * blockDim.x + threadIdx.x;
    if (i < NN) g_deg[i] = 0;
    (void)dummy;
}

// edge_index is int32 (JAX default x64-disabled downcasts int64 -> int32)
__global__ void count_deg_kernel(const int* __restrict__ ei) {
    int e = blockIdx.x * blockDim.x + threadIdx.x;
    if (e < EE) {
        int d = ei[EE + e];   // dst
        if ((unsigned)d < (unsigned)NN) atomicAdd(&g_deg[d], 1);
    }
}

// one-block exclusive scan over g_deg -> g_row_ptr, also copies to g_cursor
__global__ void scan_kernel(const float* __restrict__ dummy) {
    __shared__ int sums[1024];
    const int n = NN;
    int t = threadIdx.x;
    int chunk = (n + 1023) / 1024;           // 49
    int beg = t * chunk;
    int end = beg + chunk; if (end > n) end = n;
    if (beg > n) beg = n;
    int s = 0;
    for (int i = beg; i < end; i++) s += g_deg[i];
    sums[t] = s;
    __syncthreads();
    // inclusive Hillis-Steele scan over 1024 entries
    for (int off = 1; off < 1024; off <<= 1) {
        int v = 0;
        if (t >= off) v = sums[t - off];
        __syncthreads();
        if (t >= off) sums[t] += v;
        __syncthreads();
    }
    int run = sums[t] - s;                    // exclusive prefix for this chunk
    for (int i = beg; i < end; i++) {
        g_row_ptr[i] = run;
        g_cursor[i]  = run;
        run += g_deg[i];
    }
    if (t == 1023) g_row_ptr[n] = sums[1023];
    (void)dummy;
}

__global__ void fill_csr_kernel(const int* __restrict__ ei) {
    int e = blockIdx.x * blockDim.x + threadIdx.x;
    if (e < EE) {
        int s = ei[e];
        int d = ei[EE + e];
        if ((unsigned)d < (unsigned)NN && (unsigned)s < (unsigned)NN) {
            int p = atomicAdd(&g_cursor[d], 1);
            g_col[p] = s;
        }
    }
}

// ---------------- weight pack: Bt[k][h] = (k<256 ? Wl[h][k] : Wr[h][k-256]) ----------------
__global__ void pack_B_kernel(const float* __restrict__ W1l, const float* __restrict__ W1r,
                              const float* __restrict__ W2l, const float* __restrict__ W2r) {
    int idx = blockIdx.x * blockDim.x + threadIdx.x;   // over 2*512*256
    if (idx >= 2 * 512 * DD) return;
    int which = idx / (512 * DD);
    int rem   = idx % (512 * DD);
    int k = rem / DD;
    int h = rem % DD;
    if (which == 0) {
        g_B1[rem] = (k < DD) ? W1l[h * DD + k] : W1r[h * DD + (k - DD)];
    } else {
        g_B2[rem] = (k < DD) ? W2l[h * DD + k] : W2r[h * DD + (k - DD)];
    }
}

// ---------------- mean aggregation: 64 threads per node, float4 lanes ----------------
// feat source: layer==1 -> external x ; layer==2 -> g_h
__global__ void aggregate_kernel(const float* __restrict__ x_ext, int layer) {
    int node = blockIdx.x * 4 + (threadIdx.x >> 6);
    int lane = threadIdx.x & 63;
    if (node >= NN) return;
    const float* feat = (layer == 1) ? x_ext : (const float*)g_h;
    int beg = g_row_ptr[node];
    int end = g_row_ptr[node + 1];
    const float4* f4 = (const float4*)feat;
    float4 acc = make_float4(0.f, 0.f, 0.f, 0.f);
    for (int e = beg; e < end; e++) {
        int s = g_col[e];
        float4 v = f4[(size_t)s * 64 + lane];
        acc.x += v.x; acc.y += v.y; acc.z += v.z; acc.w += v.w;
    }
    int deg = end - beg;
    float inv = 1.0f / (float)(deg > 0 ? deg : 1);
    acc.x *= inv; acc.y *= inv; acc.z *= inv; acc.w *= inv;
    ((float4*)g_mean)[(size_t)node * 64 + lane] = acc;
}

// ---------------- fused GEMM: C = [mean | X] @ Bt + bias ----------------
// layer==1: A2 = x_ext,  Bt = g_B1, C = g_h
// layer==2: A2 = g_h,    Bt = g_B2, C = out_ext
#define BM 128
#define BN 128
#define BK 16
__global__ void __launch_bounds__(256, 2) gemm_kernel(
    const float* __restrict__ x_ext,
    const float* __restrict__ bias,
    float* __restrict__ out_ext,
    int layer, int nrows)
{
    __shared__ float As[BK][BM + 4];
    __shared__ float Bs[BK][BN];

    const float* Amean = (const float*)g_mean;
    const float* Ax    = (layer == 1) ? x_ext : (const float*)g_h;
    const float* Bt    = (layer == 1) ? (const float*)g_B1 : (const float*)g_B2;
    float*       C     = (layer == 1) ? (float*)g_h : out_ext;

    int bm = blockIdx.x * BM;
    int bn = blockIdx.y * BN;
    int tid = threadIdx.x;
    int ty = tid >> 4;         // 0..15  (m dir)
    int tx = tid & 15;         // 0..15  (n dir)

    float acc[8][8];
    #pragma unroll
    for (int i = 0; i < 8; i++)
        #pragma unroll
        for (int j = 0; j < 8; j++) acc[i][j] = 0.f;

    for (int k0 = 0; k0 < 512; k0 += BK) {
        const float* Asrc = (k0 < 256) ? Amean : Ax;
        int kk = k0 & 255;
        // A tile: 128 rows x 16 k, float4 per thread, 2 passes
        #pragma unroll
        for (int p = 0; p < 2; p++) {
            int r  = p * 64 + (tid >> 2);
            int c4 = (tid & 3) * 4;
            int gr = bm + r;
            float4 v = make_float4(0.f, 0.f, 0.f, 0.f);
            if (gr < nrows) v = *(const float4*)&Asrc[(size_t)gr * 256 + kk + c4];
            As[c4 + 0][r] = v.x;
            As[c4 + 1][r] = v.y;
            As[c4 + 2][r] = v.z;
            As[c4 + 3][r] = v.w;
        }
        // B tile: 16 k x 128 n, coalesced float4, 2 passes
        #pragma unroll
        for (int p = 0; p < 2; p++) {
            int kr = p * 8 + (tid >> 5);
            int c4 = (tid & 31) * 4;
            float4 v = *(const float4*)&Bt[(size_t)(k0 + kr) * 256 + bn + c4];
            *(float4*)&Bs[kr][c4] = v;
        }
        __syncthreads();

        #pragma unroll
        for (int k = 0; k < BK; k++) {
            float a[8], b[8];
            #pragma unroll
            for (int i = 0; i < 8; i++) a[i] = As[k][ty * 8 + i];
            #pragma unroll
            for (int j = 0; j < 8; j++) b[j] = Bs[k][tx * 8 + j];
            #pragma unroll
            for (int i = 0; i < 8; i++)
                #pragma unroll
                for (int j = 0; j < 8; j++) acc[i][j] += a[i] * b[j];
        }
        __syncthreads();
    }

    // epilogue: + bias, vectorized store
    int tn = bn + tx * 8;
    float bb[8];
    #pragma unroll
    for (int j = 0; j < 8; j++) bb[j] = bias[tn + j];
    #pragma unroll
    for (int i = 0; i < 8; i++) {
        int gr = bm + ty * 8 + i;
        if (gr < nrows) {
            float4 o0 = make_float4(acc[i][0] + bb[0], acc[i][1] + bb[1],
                                    acc[i][2] + bb[2], acc[i][3] + bb[3]);
            float4 o1 = make_float4(acc[i][4] + bb[4], acc[i][5] + bb[5],
                                    acc[i][6] + bb[6], acc[i][7] + bb[7]);
            *(float4*)&C[(size_t)gr * 256 + tn + 0] = o0;
            *(float4*)&C[(size_t)gr * 256 + tn + 4] = o1;
        }
    }
}

// ---------------- row L2 normalize (+ optional ReLU); one warp per row ----------------
// layer==1: in/out g_h (with ReLU) ; layer==2: in/out out_ext (no ReLU)
__global__ void l2norm_kernel(float* __restrict__ out_ext, int layer, int nrows) {
    int row  = blockIdx.x * 8 + (threadIdx.x >> 5);
    int lane = threadIdx.x & 31;
    if (row >= nrows) return;
    float* buf = (layer == 1) ? (float*)g_h : out_ext;
    int do_relu = (layer == 1);
    float4* p = (float4*)(buf + (size_t)row * 256);
    float4 v0 = p[lane];
    float4 v1 = p[lane + 32];
    float ss = v0.x * v0.x + v0.y * v0.y + v0.z * v0.z + v0.w * v0.w
             + v1.x * v1.x + v1.y * v1.y + v1.z * v1.z + v1.w * v1.w;
    #pragma unroll
    for (int off = 16; off >= 1; off >>= 1)
        ss += __shfl_xor_sync(0xFFFFFFFFu, ss, off);
    float inv = 1.0f / fmaxf(sqrtf(ss), 1e-12f);
    v0.x *= inv; v0.y *= inv; v0.z *= inv; v0.w *= inv;
    v1.x *= inv; v1.y *= inv; v1.z *= inv; v1.w *= inv;
    if (do_relu) {
        v0.x = fmaxf(v0.x, 0.f); v0.y = fmaxf(v0.y, 0.f);
        v0.z = fmaxf(v0.z, 0.f); v0.w = fmaxf(v0.w, 0.f);
        v1.x = fmaxf(v1.x, 0.f); v1.y = fmaxf(v1.y, 0.f);
        v1.z = fmaxf(v1.z, 0.f); v1.w = fmaxf(v1.w, 0.f);
    }
    p[lane]      = v0;
    p[lane + 32] = v1;
}

// ---------------- launch ----------------
extern "C" void kernel_launch(void* const* d_in, const int* in_sizes, int n_in,
                              void* d_out, int out_size) {
    const float* x   = (const float*)d_in[0];
    const int*   ei  = (const int*)d_in[1];   // edge_index: int32 (JAX x64 disabled)
    const float* W1l = (const float*)d_in[2];
    const float* b1l = (const float*)d_in[3];
    const float* W1r = (const float*)d_in[4];
    const float* W2l = (const float*)d_in[5];
    const float* b2l = (const float*)d_in[6];
    const float* W2r = (const float*)d_in[7];
    float* out = (float*)d_out;

    // CSR build
    zero_deg_kernel<<<(NN + 255) / 256, 256>>>(x);
    count_deg_kernel<<<(EE + 255) / 256, 256>>>(ei);
    scan_kernel<<<1, 1024>>>(x);
    fill_csr_kernel<<<(EE + 255) / 256, 256>>>(ei);

    // weight pack
    pack_B_kernel<<<(2 * 512 * DD + 255) / 256, 256>>>(W1l, W1r, W2l, W2r);

    dim3 ggrid((NN + BM - 1) / BM, DD / BN);

    // ---- layer 1 ----
    aggregate_kernel<<<(NN + 3) / 4, 256>>>(x, 1);
    gemm_kernel<<<ggrid, 256>>>(x, b1l, out, 1, NN);
    l2norm_kernel<<<(NN + 7) / 8, 256>>>(out, 1, NN);

    // ---- layer 2 ----
    aggregate_kernel<<<(NN + 3) / 4, 256>>>(x, 2);
    gemm_kernel<<<ggrid, 256>>>(x, b2l, out, 2, NN);
    l2norm_kernel<<<(NN + 7) / 8, 256>>>(out, 2, NN);
}

// round 5
// speedup vs baseline: 1.5487x; 1.5487x over previous
#include <cuda_runtime.h>
#include <cuda_bf16.h>
#include <cstdint>

#define NN 50000
#define EE 800000
#define DD 256

// ---------------- scratch (static device globals; no allocation) ----------------
__device__ int   g_deg[NN];
__device__ int   g_row_ptr[NN + 1];
__device__ int   g_cursor[NN];
__device__ int   g_col[EE];
__device__ __align__(16) float g_mean[(size_t)NN * DD];   // aggregated (mean) features
__device__ __align__(16) float g_h[(size_t)NN * DD];      // layer-1 output (normalized+relu)
// packed weights, bf16 hi/lo split: [layer][h=256][k=512], k-major
__device__ __align__(16) __nv_bfloat16 g_Bh[2 * 256 * 512];
__device__ __align__(16) __nv_bfloat16 g_Bl[2 * 256 * 512];

__device__ __forceinline__ uint32_t smem_u32(const void* p) {
    uint32_t a;
    asm("{ .reg .u64 t; cvta.to.shared.u64 t, %1; cvt.u32.u64 %0, t; }" : "=r"(a) : "l"(p));
    return a;
}

// ---------------- CSR build ----------------
__global__ void zero_deg_kernel(const float* __restrict__ dummy) {
    int i = blockIdx.x * blockDim.x + threadIdx.x;
    if (i < NN) g_deg[i] = 0;
    (void)dummy;
}

__global__ void count_deg_kernel(const int* __restrict__ ei) {
    int e = blockIdx.x * blockDim.x + threadIdx.x;
    if (e < EE) {
        int d = ei[EE + e];
        if ((unsigned)d < (unsigned)NN) atomicAdd(&g_deg[d], 1);
    }
}

__global__ void scan_kernel(const float* __restrict__ dummy) {
    __shared__ int sums[1024];
    const int n = NN;
    int t = threadIdx.x;
    int chunk = (n + 1023) / 1024;
    int beg = t * chunk;
    int end = beg + chunk; if (end > n) end = n;
    if (beg > n) beg = n;
    int s = 0;
    for (int i = beg; i < end; i++) s += g_deg[i];
    sums[t] = s;
    __syncthreads();
    for (int off = 1; off < 1024; off <<= 1) {
        int v = 0;
        if (t >= off) v = sums[t - off];
        __syncthreads();
        if (t >= off) sums[t] += v;
        __syncthreads();
    }
    int run = sums[t] - s;
    for (int i = beg; i < end; i++) {
        g_row_ptr[i] = run;
        g_cursor[i]  = run;
        run += g_deg[i];
    }
    if (t == 1023) g_row_ptr[n] = sums[1023];
    (void)dummy;
}

__global__ void fill_csr_kernel(const int* __restrict__ ei) {
    int e = blockIdx.x * blockDim.x + threadIdx.x;
    if (e < EE) {
        int s = ei[e];
        int d = ei[EE + e];
        if ((unsigned)d < (unsigned)NN && (unsigned)s < (unsigned)NN) {
            int p = atomicAdd(&g_cursor[d], 1);
            g_col[p] = s;
        }
    }
}

// ---------------- weight pack -> bf16 hi/lo, layout [layer][h][k] ----------------
__global__ void pack_B_kernel(const float* __restrict__ W1l, const float* __restrict__ W1r,
                              const float* __restrict__ W2l, const float* __restrict__ W2r) {
    int idx = blockIdx.x * blockDim.x + threadIdx.x;     // 2*256*512
    if (idx >= 2 * 256 * 512) return;
    int layer = idx >> 17;
    int rem   = idx & 131071;
    int h = rem >> 9;
    int k = rem & 511;
    const float* Wl = layer ? W2l : W1l;
    const float* Wr = layer ? W2r : W1r;
    float v = (k < 256) ? Wl[h * 256 + k] : Wr[h * 256 + (k - 256)];
    __nv_bfloat16 hi = __float2bfloat16_rn(v);
    __nv_bfloat16 lo = __float2bfloat16_rn(v - __bfloat162float(hi));
    g_Bh[idx] = hi;
    g_Bl[idx] = lo;
}

// ---------------- mean aggregation: 64 threads per node, float4 lanes ----------------
__global__ void aggregate_kernel(const float* __restrict__ x_ext, int layer) {
    int node = blockIdx.x * 4 + (threadIdx.x >> 6);
    int lane = threadIdx.x & 63;
    if (node >= NN) return;
    const float* feat = (layer == 1) ? x_ext : (const float*)g_h;
    int beg = g_row_ptr[node];
    int end = g_row_ptr[node + 1];
    const float4* f4 = (const float4*)feat;
    float4 acc = make_float4(0.f, 0.f, 0.f, 0.f);
    for (int e = beg; e < end; e++) {
        int s = g_col[e];
        float4 v = f4[(size_t)s * 64 + lane];
        acc.x += v.x; acc.y += v.y; acc.z += v.z; acc.w += v.w;
    }
    int deg = end - beg;
    float inv = 1.0f / (float)(deg > 0 ? deg : 1);
    acc.x *= inv; acc.y *= inv; acc.z *= inv; acc.w *= inv;
    ((float4*)g_mean)[(size_t)node * 64 + lane] = acc;
}

// ---------------- bf16x3 HMMA GEMM + fused bias/L2norm/ReLU epilogue ----------------
// C[node][h] = normalize( sum_k [mean|feat][node][k] * Wcat[h][k] + bias[h] ) (relu if layer1)
// BM=64 rows/CTA, BN=256 (full width), BK=32; 8 warps (wm 0..1 x wn 0..3), warp tile 32x64.
#define PAD 40
#define OFF_A_HI 0
#define OFF_A_LO 5120
#define OFF_B_HI 10240
#define OFF_B_LO 30720
#define OFF_RED  51200
#define SMEM_DYN 52224

__device__ __forceinline__ void ldm4(uint32_t* r, uint32_t addr) {
    asm volatile("ldmatrix.sync.aligned.m8n8.x4.shared.b16 {%0,%1,%2,%3}, [%4];"
                 : "=r"(r[0]), "=r"(r[1]), "=r"(r[2]), "=r"(r[3]) : "r"(addr));
}
__device__ __forceinline__ void mma16816(float* c, const uint32_t* a, uint32_t b0, uint32_t b1) {
    asm volatile("mma.sync.aligned.m16n8k16.row.col.f32.bf16.bf16.f32 "
                 "{%0,%1,%2,%3}, {%4,%5,%6,%7}, {%8,%9}, {%0,%1,%2,%3};"
                 : "+f"(c[0]), "+f"(c[1]), "+f"(c[2]), "+f"(c[3])
                 : "r"(a[0]), "r"(a[1]), "r"(a[2]), "r"(a[3]), "r"(b0), "r"(b1));
}

__global__ void __launch_bounds__(256) gemm_kernel(
    const float* __restrict__ x_ext,
    const float* __restrict__ bias,
    float* __restrict__ out_ext,
    int layer)
{
    extern __shared__ char sm[];
    float* red = (float*)(sm + OFF_RED);

    int tid  = threadIdx.x;
    int lane = tid & 31;
    int wid  = tid >> 5;
    int wm = wid >> 2;         // 0..1
    int wn = wid & 3;          // 0..3
    int bm = blockIdx.x * 64;

    const float* Amean = (const float*)g_mean;
    const float* Ax    = (layer == 1) ? x_ext : (const float*)g_h;
    const __nv_bfloat16* Bh = g_Bh + (size_t)(layer - 1) * 131072;
    const __nv_bfloat16* Bl = g_Bl + (size_t)(layer - 1) * 131072;
    float* C = (layer == 1) ? (float*)g_h : out_ext;

    float acc[2][8][4];
    #pragma unroll
    for (int i = 0; i < 2; i++)
        #pragma unroll
        for (int j = 0; j < 8; j++)
            #pragma unroll
            for (int q = 0; q < 4; q++) acc[i][j][q] = 0.f;

    // ldmatrix per-lane address components
    uint32_t aBase = smem_u32(sm + OFF_A_HI);
    uint32_t bBase = smem_u32(sm + OFF_B_HI);
    int arow_l = (((lane >> 3) & 1) << 3) + (lane & 7);
    int akc_l  = ((lane >> 4) & 1) << 3;
    int brow_l = (((lane >> 4) & 1) << 3) + (lane & 7);
    int bkc_l  = ((lane >> 3) & 1) << 3;

    for (int kc = 0; kc < 16; kc++) {
        const float* Asrc = (kc < 8) ? Amean : Ax;
        int kk = (kc & 7) * 32;

        // A: 64 rows x 32 fp32 -> bf16 hi/lo (stride PAD)
        #pragma unroll
        for (int p = 0; p < 2; p++) {
            int idx = tid + p * 256;
            int row = idx >> 3;
            int q   = idx & 7;
            int gr  = bm + row;
            float4 v = make_float4(0.f, 0.f, 0.f, 0.f);
            if (gr < NN) v = *(const float4*)&Asrc[(size_t)gr * 256 + kk + q * 4];
            __nv_bfloat16 h0 = __float2bfloat16_rn(v.x);
            __nv_bfloat16 h1 = __float2bfloat16_rn(v.y);
            __nv_bfloat16 h2 = __float2bfloat16_rn(v.z);
            __nv_bfloat16 h3 = __float2bfloat16_rn(v.w);
            __nv_bfloat16 l0 = __float2bfloat16_rn(v.x - __bfloat162float(h0));
            __nv_bfloat16 l1 = __float2bfloat16_rn(v.y - __bfloat162float(h1));
            __nv_bfloat16 l2 = __float2bfloat16_rn(v.z - __bfloat162float(h2));
            __nv_bfloat16 l3 = __float2bfloat16_rn(v.w - __bfloat162float(h3));
            uint2 uh = make_uint2(
                (uint32_t)__bfloat16_as_ushort(h0) | ((uint32_t)__bfloat16_as_ushort(h1) << 16),
                (uint32_t)__bfloat16_as_ushort(h2) | ((uint32_t)__bfloat16_as_ushort(h3) << 16));
            uint2 ul = make_uint2(
                (uint32_t)__bfloat16_as_ushort(l0) | ((uint32_t)__bfloat16_as_ushort(l1) << 16),
                (uint32_t)__bfloat16_as_ushort(l2) | ((uint32_t)__bfloat16_as_ushort(l3) << 16));
            int boff = (row * PAD + q * 4) * 2;
            *(uint2*)(sm + OFF_A_HI + boff) = uh;
            *(uint2*)(sm + OFF_A_LO + boff) = ul;
        }
        // B: 256 rows x 32 bf16 (pre-split) -> smem (stride PAD)
        #pragma unroll
        for (int p = 0; p < 4; p++) {
            int idx = tid + p * 256;
            int row = idx >> 2;
            int u   = idx & 3;
            size_t goff = (size_t)row * 512 + kc * 32 + u * 8;
            uint4 vh = *(const uint4*)(Bh + goff);
            uint4 vl = *(const uint4*)(Bl + goff);
            int boff = (row * PAD + u * 8) * 2;
            *(uint4*)(sm + OFF_B_HI + boff) = vh;
            *(uint4*)(sm + OFF_B_LO + boff) = vl;
        }
        __syncthreads();

        #pragma unroll
        for (int ks = 0; ks < 2; ks++) {
            uint32_t aHi[2][4], aLo[2][4], bHi[4][4], bLo[4][4];
            #pragma unroll
            for (int ms = 0; ms < 2; ms++) {
                uint32_t ao = (uint32_t)(((wm * 32 + ms * 16 + arow_l) * PAD + ks * 16 + akc_l) * 2);
                ldm4(aHi[ms], aBase + ao);
                ldm4(aLo[ms], aBase + (uint32_t)(OFF_A_LO - OFF_A_HI) + ao);
            }
            #pragma unroll
            for (int ng = 0; ng < 4; ng++) {
                uint32_t bo = (uint32_t)(((wn * 64 + ng * 16 + brow_l) * PAD + ks * 16 + bkc_l) * 2);
                ldm4(bHi[ng], bBase + bo);
                ldm4(bLo[ng], bBase + (uint32_t)(OFF_B_LO - OFF_B_HI) + bo);
            }
            #pragma unroll
            for (int ms = 0; ms < 2; ms++) {
                #pragma unroll
                for (int nt = 0; nt < 8; nt++) {
                    int ng = nt >> 1;
                    int sl = (nt & 1) * 2;
                    mma16816(acc[ms][nt], aHi[ms], bHi[ng][sl], bHi[ng][sl + 1]);
                    mma16816(acc[ms][nt], aHi[ms], bLo[ng][sl], bLo[ng][sl + 1]);
                    mma16816(acc[ms][nt], aLo[ms], bHi[ng][sl], bHi[ng][sl + 1]);
                }
            }
        }
        __syncthreads();
    }

    // ---- epilogue: bias, row L2 norm across warps, (relu), store ----
    #pragma unroll
    for (int ms = 0; ms < 2; ms++) {
        int r0 = wm * 32 + ms * 16 + (lane >> 2);
        float ss0 = 0.f, ss1 = 0.f;
        #pragma unroll
        for (int nt = 0; nt < 8; nt++) {
            int col = wn * 64 + nt * 8 + (lane & 3) * 2;
            float b0 = bias[col], b1 = bias[col + 1];
            acc[ms][nt][0] += b0; acc[ms][nt][1] += b1;
            acc[ms][nt][2] += b0; acc[ms][nt][3] += b1;
            ss0 += acc[ms][nt][0] * acc[ms][nt][0] + acc[ms][nt][1] * acc[ms][nt][1];
            ss1 += acc[ms][nt][2] * acc[ms][nt][2] + acc[ms][nt][3] * acc[ms][nt][3];
        }
        ss0 += __shfl_xor_sync(0xFFFFFFFFu, ss0, 1);
        ss0 += __shfl_xor_sync(0xFFFFFFFFu, ss0, 2);
        ss1 += __shfl_xor_sync(0xFFFFFFFFu, ss1, 1);
        ss1 += __shfl_xor_sync(0xFFFFFFFFu, ss1, 2);
        if ((lane & 3) == 0) {
            red[r0 * 4 + wn]       = ss0;
            red[(r0 + 8) * 4 + wn] = ss1;
        }
    }
    __syncthreads();

    int do_relu = (layer == 1);
    #pragma unroll
    for (int ms = 0; ms < 2; ms++) {
        int r0 = wm * 32 + ms * 16 + (lane >> 2);
        float s0 = red[r0 * 4 + 0] + red[r0 * 4 + 1] + red[r0 * 4 + 2] + red[r0 * 4 + 3];
        float s1 = red[(r0 + 8) * 4 + 0] + red[(r0 + 8) * 4 + 1]
                 + red[(r0 + 8) * 4 + 2] + red[(r0 + 8) * 4 + 3];
        float inv0 = 1.0f / fmaxf(sqrtf(s0), 1e-12f);
        float inv1 = 1.0f / fmaxf(sqrtf(s1), 1e-12f);
        int gr0 = bm + r0;
        int gr1 = gr0 + 8;
        #pragma unroll
        for (int nt = 0; nt < 8; nt++) {
            int col = wn * 64 + nt * 8 + (lane & 3) * 2;
            if (gr0 < NN) {
                float o0 = acc[ms][nt][0] * inv0;
                float o1 = acc[ms][nt][1] * inv0;
                if (do_relu) { o0 = fmaxf(o0, 0.f); o1 = fmaxf(o1, 0.f); }
                *(float2*)&C[(size_t)gr0 * 256 + col] = make_float2(o0, o1);
            }
            if (gr1 < NN) {
                float o2 = acc[ms][nt][2] * inv1;
                float o3 = acc[ms][nt][3] * inv1;
                if (do_relu) { o2 = fmaxf(o2, 0.f); o3 = fmaxf(o3, 0.f); }
                *(float2*)&C[(size_t)gr1 * 256 + col] = make_float2(o2, o3);
            }
        }
    }
}

// ---------------- launch ----------------
extern "C" void kernel_launch(void* const* d_in, const int* in_sizes, int n_in,
                              void* d_out, int out_size) {
    const float* x   = (const float*)d_in[0];
    const int*   ei  = (const int*)d_in[1];   // edge_index: int32
    const float* W1l = (const float*)d_in[2];
    const float* b1l = (const float*)d_in[3];
    const float* W1r = (const float*)d_in[4];
    const float* W2l = (const float*)d_in[5];
    const float* b2l = (const float*)d_in[6];
    const float* W2r = (const float*)d_in[7];
    float* out = (float*)d_out;

    cudaFuncSetAttribute(gemm_kernel, cudaFuncAttributeMaxDynamicSharedMemorySize, SMEM_DYN);

    // CSR build
    zero_deg_kernel<<<(NN + 255) / 256, 256>>>(x);
    count_deg_kernel<<<(EE + 255) / 256, 256>>>(ei);
    scan_kernel<<<1, 1024>>>(x);
    fill_csr_kernel<<<(EE + 255) / 256, 256>>>(ei);

    // weight pack (bf16 hi/lo)
    pack_B_kernel<<<(2 * 256 * 512 + 255) / 256, 256>>>(W1l, W1r, W2l, W2r);

    int gemm_grid = (NN + 63) / 64;   // 782

    // ---- layer 1 ----
    aggregate_kernel<<<(NN + 3) / 4, 256>>>(x, 1);
    gemm_kernel<<<gemm_grid, 256, SMEM_DYN>>>(x, b1l, out, 1);

    // ---- layer 2 ----
    aggregate_kernel<<<(NN + 3) / 4, 256>>>(x, 2);
    gemm_kernel<<<gemm_grid, 256, SMEM_DYN>>>(x, b2l, out, 2);
}

// round 6
// speedup vs baseline: 1.6966x; 1.0955x over previous
#include <cuda_runtime.h>
#include <cuda_bf16.h>
#include <cstdint>

#define NN 50000
#define EE 800000
#define DD 256

// ---------------- scratch (static device globals; no allocation) ----------------
__device__ int   g_deg[NN];
__device__ int   g_row_ptr[NN + 1];
__device__ int   g_cursor[NN];
__device__ int   g_col[EE];
__device__ __align__(16) float g_mean[(size_t)NN * DD];   // aggregated (mean) features
__device__ __align__(16) float g_h[(size_t)NN * DD];      // layer-1 output (normalized+relu)
// packed weights, bf16 hi/lo split: [layer][h=256][k=512], k-major
__device__ __align__(16) __nv_bfloat16 g_Bh[2 * 256 * 512];
__device__ __align__(16) __nv_bfloat16 g_Bl[2 * 256 * 512];

__device__ __forceinline__ uint32_t smem_u32(const void* p) {
    uint32_t a;
    asm("{ .reg .u64 t; cvta.to.shared.u64 t, %1; cvt.u32.u64 %0, t; }" : "=r"(a) : "l"(p));
    return a;
}

// ---------------- CSR build ----------------
__global__ void zero_deg_kernel(const float* __restrict__ dummy) {
    int i = blockIdx.x * blockDim.x + threadIdx.x;
    if (i < NN) g_deg[i] = 0;
    (void)dummy;
}

__global__ void count_deg_kernel(const int* __restrict__ ei) {
    int e = blockIdx.x * blockDim.x + threadIdx.x;
    if (e < EE) {
        int d = ei[EE + e];
        if ((unsigned)d < (unsigned)NN) atomicAdd(&g_deg[d], 1);
    }
}

__global__ void scan_kernel(const float* __restrict__ dummy) {
    __shared__ int sums[1024];
    const int n = NN;
    int t = threadIdx.x;
    int chunk = (n + 1023) / 1024;
    int beg = t * chunk;
    int end = beg + chunk; if (end > n) end = n;
    if (beg > n) beg = n;
    int s = 0;
    for (int i = beg; i < end; i++) s += g_deg[i];
    sums[t] = s;
    __syncthreads();
    for (int off = 1; off < 1024; off <<= 1) {
        int v = 0;
        if (t >= off) v = sums[t - off];
        __syncthreads();
        if (t >= off) sums[t] += v;
        __syncthreads();
    }
    int run = sums[t] - s;
    for (int i = beg; i < end; i++) {
        g_row_ptr[i] = run;
        g_cursor[i]  = run;
        run += g_deg[i];
    }
    if (t == 1023) g_row_ptr[n] = sums[1023];
    (void)dummy;
}

__global__ void fill_csr_kernel(const int* __restrict__ ei) {
    int e = blockIdx.x * blockDim.x + threadIdx.x;
    if (e < EE) {
        int s = ei[e];
        int d = ei[EE + e];
        if ((unsigned)d < (unsigned)NN && (unsigned)s < (unsigned)NN) {
            int p = atomicAdd(&g_cursor[d], 1);
            g_col[p] = s;
        }
    }
}

// ---------------- weight pack -> bf16 hi/lo, layout [layer][h][k] ----------------
__global__ void pack_B_kernel(const float* __restrict__ W1l, const float* __restrict__ W1r,
                              const float* __restrict__ W2l, const float* __restrict__ W2r) {
    int idx = blockIdx.x * blockDim.x + threadIdx.x;     // 2*256*512
    if (idx >= 2 * 256 * 512) return;
    int layer = idx >> 17;
    int rem   = idx & 131071;
    int h = rem >> 9;
    int k = rem & 511;
    const float* Wl = layer ? W2l : W1l;
    const float* Wr = layer ? W2r : W1r;
    float v = (k < 256) ? Wl[h * 256 + k] : Wr[h * 256 + (k - 256)];
    __nv_bfloat16 hi = __float2bfloat16_rn(v);
    __nv_bfloat16 lo = __float2bfloat16_rn(v - __bfloat162float(hi));
    g_Bh[idx] = hi;
    g_Bl[idx] = lo;
}

// ---------------- mean aggregation: 64 threads per node, unroll-4 for MLP ----------------
__global__ void aggregate_kernel(const float* __restrict__ x_ext, int layer) {
    int node = blockIdx.x * 4 + (threadIdx.x >> 6);
    int lane = threadIdx.x & 63;
    if (node >= NN) return;
    const float* feat = (layer == 1) ? x_ext : (const float*)g_h;
    int beg = g_row_ptr[node];
    int end = g_row_ptr[node + 1];
    const float4* f4 = (const float4*)feat;
    float4 a0 = make_float4(0.f, 0.f, 0.f, 0.f);
    float4 a1 = make_float4(0.f, 0.f, 0.f, 0.f);
    int e = beg;
    for (; e + 4 <= end; e += 4) {
        int s0 = g_col[e + 0];
        int s1 = g_col[e + 1];
        int s2 = g_col[e + 2];
        int s3 = g_col[e + 3];
        float4 v0 = f4[(size_t)s0 * 64 + lane];
        float4 v1 = f4[(size_t)s1 * 64 + lane];
        float4 v2 = f4[(size_t)s2 * 64 + lane];
        float4 v3 = f4[(size_t)s3 * 64 + lane];
        a0.x += v0.x; a0.y += v0.y; a0.z += v0.z; a0.w += v0.w;
        a1.x += v1.x; a1.y += v1.y; a1.z += v1.z; a1.w += v1.w;
        a0.x += v2.x; a0.y += v2.y; a0.z += v2.z; a0.w += v2.w;
        a1.x += v3.x; a1.y += v3.y; a1.z += v3.z; a1.w += v3.w;
    }
    for (; e < end; e++) {
        int s = g_col[e];
        float4 v = f4[(size_t)s * 64 + lane];
        a0.x += v.x; a0.y += v.y; a0.z += v.z; a0.w += v.w;
    }
    float4 acc;
    acc.x = a0.x + a1.x; acc.y = a0.y + a1.y;
    acc.z = a0.z + a1.z; acc.w = a0.w + a1.w;
    int deg = end - beg;
    float inv = 1.0f / (float)(deg > 0 ? deg : 1);
    acc.x *= inv; acc.y *= inv; acc.z *= inv; acc.w *= inv;
    ((float4*)g_mean)[(size_t)node * 64 + lane] = acc;
}

// ---------------- bf16x3 HMMA GEMM + fused bias/L2norm/ReLU epilogue ----------------
// BM=128 rows/CTA, BN=256 (full width), BK=32; 16 warps (wm 0..3 x wn 0..3), warp tile 32x64.
#define PAD 40
#define OFF_A_HI 0
#define OFF_A_LO 10240
#define OFF_B_HI 20480
#define OFF_B_LO 40960
#define OFF_RED  61440
#define SMEM_DYN 63488

__device__ __forceinline__ void ldm4(uint32_t* r, uint32_t addr) {
    asm volatile("ldmatrix.sync.aligned.m8n8.x4.shared.b16 {%0,%1,%2,%3}, [%4];"
                 : "=r"(r[0]), "=r"(r[1]), "=r"(r[2]), "=r"(r[3]) : "r"(addr));
}
__device__ __forceinline__ void mma16816(float* c, const uint32_t* a, uint32_t b0, uint32_t b1) {
    asm volatile("mma.sync.aligned.m16n8k16.row.col.f32.bf16.bf16.f32 "
                 "{%0,%1,%2,%3}, {%4,%5,%6,%7}, {%8,%9}, {%0,%1,%2,%3};"
                 : "+f"(c[0]), "+f"(c[1]), "+f"(c[2]), "+f"(c[3])
                 : "r"(a[0]), "r"(a[1]), "r"(a[2]), "r"(a[3]), "r"(b0), "r"(b1));
}

__global__ void __launch_bounds__(512) gemm_kernel(
    const float* __restrict__ x_ext,
    const float* __restrict__ bias,
    float* __restrict__ out_ext,
    int layer)
{
    extern __shared__ char sm[];
    float* red = (float*)(sm + OFF_RED);

    int tid  = threadIdx.x;
    int lane = tid & 31;
    int wid  = tid >> 5;
    int wm = wid >> 2;         // 0..3
    int wn = wid & 3;          // 0..3
    int bm = blockIdx.x * 128;

    const float* Amean = (const float*)g_mean;
    const float* Ax    = (layer == 1) ? x_ext : (const float*)g_h;
    const __nv_bfloat16* Bh = g_Bh + (size_t)(layer - 1) * 131072;
    const __nv_bfloat16* Bl = g_Bl + (size_t)(layer - 1) * 131072;
    float* C = (layer == 1) ? (float*)g_h : out_ext;

    float acc[2][8][4];
    #pragma unroll
    for (int i = 0; i < 2; i++)
        #pragma unroll
        for (int j = 0; j < 8; j++)
            #pragma unroll
            for (int q = 0; q < 4; q++) acc[i][j][q] = 0.f;

    uint32_t aBase = smem_u32(sm + OFF_A_HI);
    uint32_t bBase = smem_u32(sm + OFF_B_HI);
    int arow_l = (((lane >> 3) & 1) << 3) + (lane & 7);
    int akc_l  = ((lane >> 4) & 1) << 3;
    int brow_l = (((lane >> 4) & 1) << 3) + (lane & 7);
    int bkc_l  = ((lane >> 3) & 1) << 3;

    for (int kc = 0; kc < 16; kc++) {
        const float* Asrc = (kc < 8) ? Amean : Ax;
        int kk = (kc & 7) * 32;

        // A: 128 rows x 32 fp32 -> bf16 hi/lo (stride PAD); 1024 float4 slots, 512 thr x2
        #pragma unroll
        for (int p = 0; p < 2; p++) {
            int idx = tid + p * 512;
            int row = idx >> 3;
            int q   = idx & 7;
            int gr  = bm + row;
            float4 v = make_float4(0.f, 0.f, 0.f, 0.f);
            if (gr < NN) v = *(const float4*)&Asrc[(size_t)gr * 256 + kk + q * 4];
            __nv_bfloat16 h0 = __float2bfloat16_rn(v.x);
            __nv_bfloat16 h1 = __float2bfloat16_rn(v.y);
            __nv_bfloat16 h2 = __float2bfloat16_rn(v.z);
            __nv_bfloat16 h3 = __float2bfloat16_rn(v.w);
            __nv_bfloat16 l0 = __float2bfloat16_rn(v.x - __bfloat162float(h0));
            __nv_bfloat16 l1 = __float2bfloat16_rn(v.y - __bfloat162float(h1));
            __nv_bfloat16 l2 = __float2bfloat16_rn(v.z - __bfloat162float(h2));
            __nv_bfloat16 l3 = __float2bfloat16_rn(v.w - __bfloat162float(h3));
            uint2 uh = make_uint2(
                (uint32_t)__bfloat16_as_ushort(h0) | ((uint32_t)__bfloat16_as_ushort(h1) << 16),
                (uint32_t)__bfloat16_as_ushort(h2) | ((uint32_t)__bfloat16_as_ushort(h3) << 16));
            uint2 ul = make_uint2(
                (uint32_t)__bfloat16_as_ushort(l0) | ((uint32_t)__bfloat16_as_ushort(l1) << 16),
                (uint32_t)__bfloat16_as_ushort(l2) | ((uint32_t)__bfloat16_as_ushort(l3) << 16));
            int boff = (row * PAD + q * 4) * 2;
            *(uint2*)(sm + OFF_A_HI + boff) = uh;
            *(uint2*)(sm + OFF_A_LO + boff) = ul;
        }
        // B: 256 rows x 32 bf16 (pre-split) -> smem; 1024 uint4 slots, 512 thr x2
        #pragma unroll
        for (int p = 0; p < 2; p++) {
            int idx = tid + p * 512;
            int row = idx >> 2;
            int u   = idx & 3;
            size_t goff = (size_t)row * 512 + kc * 32 + u * 8;
            uint4 vh = *(const uint4*)(Bh + goff);
            uint4 vl = *(const uint4*)(Bl + goff);
            int boff = (row * PAD + u * 8) * 2;
            *(uint4*)(sm + OFF_B_HI + boff) = vh;
            *(uint4*)(sm + OFF_B_LO + boff) = vl;
        }
        __syncthreads();

        #pragma unroll
        for (int ks = 0; ks < 2; ks++) {
            uint32_t aHi[2][4], aLo[2][4];
            #pragma unroll
            for (int ms = 0; ms < 2; ms++) {
                uint32_t ao = (uint32_t)(((wm * 32 + ms * 16 + arow_l) * PAD + ks * 16 + akc_l) * 2);
                ldm4(aHi[ms], aBase + ao);
                ldm4(aLo[ms], aBase + (uint32_t)(OFF_A_LO - OFF_A_HI) + ao);
            }
            #pragma unroll
            for (int ng = 0; ng < 4; ng++) {
                uint32_t bH[4], bL[4];
                uint32_t bo = (uint32_t)(((wn * 64 + ng * 16 + brow_l) * PAD + ks * 16 + bkc_l) * 2);
                ldm4(bH, bBase + bo);
                ldm4(bL, bBase + (uint32_t)(OFF_B_LO - OFF_B_HI) + bo);
                #pragma unroll
                for (int ms = 0; ms < 2; ms++) {
                    #pragma unroll
                    for (int sl = 0; sl < 2; sl++) {
                        int nt = ng * 2 + sl;
                        mma16816(acc[ms][nt], aHi[ms], bH[sl * 2], bH[sl * 2 + 1]);
                        mma16816(acc[ms][nt], aHi[ms], bL[sl * 2], bL[sl * 2 + 1]);
                        mma16816(acc[ms][nt], aLo[ms], bH[sl * 2], bH[sl * 2 + 1]);
                    }
                }
            }
        }
        __syncthreads();
    }

    // ---- epilogue: bias, row L2 norm across warps, (relu), store ----
    #pragma unroll
    for (int ms = 0; ms < 2; ms++) {
        int r0 = wm * 32 + ms * 16 + (lane >> 2);
        float ss0 = 0.f, ss1 = 0.f;
        #pragma unroll
        for (int nt = 0; nt < 8; nt++) {
            int col = wn * 64 + nt * 8 + (lane & 3) * 2;
            float b0 = bias[col], b1 = bias[col + 1];
            acc[ms][nt][0] += b0; acc[ms][nt][1] += b1;
            acc[ms][nt][2] += b0; acc[ms][nt][3] += b1;
            ss0 += acc[ms][nt][0] * acc[ms][nt][0] + acc[ms][nt][1] * acc[ms][nt][1];
            ss1 += acc[ms][nt][2] * acc[ms][nt][2] + acc[ms][nt][3] * acc[ms][nt][3];
        }
        ss0 += __shfl_xor_sync(0xFFFFFFFFu, ss0, 1);
        ss0 += __shfl_xor_sync(0xFFFFFFFFu, ss0, 2);
        ss1 += __shfl_xor_sync(0xFFFFFFFFu, ss1, 1);
        ss1 += __shfl_xor_sync(0xFFFFFFFFu, ss1, 2);
        if ((lane & 3) == 0) {
            red[r0 * 4 + wn]       = ss0;
            red[(r0 + 8) * 4 + wn] = ss1;
        }
    }
    __syncthreads();

    int do_relu = (layer == 1);
    #pragma unroll
    for (int ms = 0; ms < 2; ms++) {
        int r0 = wm * 32 + ms * 16 + (lane >> 2);
        float s0 = red[r0 * 4 + 0] + red[r0 * 4 + 1] + red[r0 * 4 + 2] + red[r0 * 4 + 3];
        float s1 = red[(r0 + 8) * 4 + 0] + red[(r0 + 8) * 4 + 1]
                 + red[(r0 + 8) * 4 + 2] + red[(r0 + 8) * 4 + 3];
        float inv0 = 1.0f / fmaxf(sqrtf(s0), 1e-12f);
        float inv1 = 1.0f / fmaxf(sqrtf(s1), 1e-12f);
        int gr0 = bm + r0;
        int gr1 = gr0 + 8;
        #pragma unroll
        for (int nt = 0; nt < 8; nt++) {
            int col = wn * 64 + nt * 8 + (lane & 3) * 2;
            if (gr0 < NN) {
                float o0 = acc[ms][nt][0] * inv0;
                float o1 = acc[ms][nt][1] * inv0;
                if (do_relu) { o0 = fmaxf(o0, 0.f); o1 = fmaxf(o1, 0.f); }
                *(float2*)&C[(size_t)gr0 * 256 + col] = make_float2(o0, o1);
            }
            if (gr1 < NN) {
                float o2 = acc[ms][nt][2] * inv1;
                float o3 = acc[ms][nt][3] * inv1;
                if (do_relu) { o2 = fmaxf(o2, 0.f); o3 = fmaxf(o3, 0.f); }
                *(float2*)&C[(size_t)gr1 * 256 + col] = make_float2(o2, o3);
            }
        }
    }
}

// ---------------- launch ----------------
extern "C" void kernel_launch(void* const* d_in, const int* in_sizes, int n_in,
                              void* d_out, int out_size) {
    const float* x   = (const float*)d_in[0];
    const int*   ei  = (const int*)d_in[1];   // edge_index: int32
    const float* W1l = (const float*)d_in[2];
    const float* b1l = (const float*)d_in[3];
    const float* W1r = (const float*)d_in[4];
    const float* W2l = (const float*)d_in[5];
    const float* b2l = (const float*)d_in[6];
    const float* W2r = (const float*)d_in[7];
    float* out = (float*)d_out;

    cudaFuncSetAttribute(gemm_kernel, cudaFuncAttributeMaxDynamicSharedMemorySize, SMEM_DYN);

    // CSR build
    zero_deg_kernel<<<(NN + 255) / 256, 256>>>(x);
    count_deg_kernel<<<(EE + 255) / 256, 256>>>(ei);
    scan_kernel<<<1, 1024>>>(x);
    fill_csr_kernel<<<(EE + 255) / 256, 256>>>(ei);

    // weight pack (bf16 hi/lo)
    pack_B_kernel<<<(2 * 256 * 512 + 255) / 256, 256>>>(W1l, W1r, W2l, W2r);

    int gemm_grid = (NN + 127) / 128;   // 391

    // ---- layer 1 ----
    aggregate_kernel<<<(NN + 3) / 4, 256>>>(x, 1);
    gemm_kernel<<<gemm_grid, 512, SMEM_DYN>>>(x, b1l, out, 1);

    // ---- layer 2 ----
    aggregate_kernel<<<(NN + 3) / 4, 256>>>(x, 2);
    gemm_kernel<<<gemm_grid, 512, SMEM_DYN>>>(x, b2l, out, 2);
}